// round 15
// baseline (speedup 1.0000x reference)
#include <cuda_runtime.h>
#include <cuda_fp16.h>
#include <math_constants.h>
#include <cstdint>

// Problem constants (fixed by the dataset)
#define Nn   20000
#define Ee   100000
#define INDIM 256
#define Dd   512
#define Hh   4
#define HD   2048        // Hh * Dd
#define FW   (2 * HD)    // fused feature row: [fs | fd]
#define SLOPE 0.2f

// ---------------------------------------------------------------------------
// Scratch (device globals: allocation-free per harness rules)
// ---------------------------------------------------------------------------
__device__ __half g_feat[(size_t)Nn * FW];     // 164 MB: row = [fs(2048) | fd(2048)]
__device__ __half g_rp  [(size_t)Nn * HD];     // 82 MB (aggregated feats)
__device__ float  g_effbias[Dd];
__device__ float  g_biascat[FW];               // [b_src | b_dst]

// CSR over dst
__device__ int g_deg[Nn];
__device__ int g_rowptr[Nn];
__device__ int g_cursor[Nn];
__device__ int g_eidx[Ee];

// fp16 casts
__device__ __half g_zp[(size_t)Nn * INDIM];    // 10.2 MB
__device__ __half g_w [(size_t)INDIM * FW];    // 2.1 MB: [W_src | W_dst] cols
__device__ __half g_wfp[(size_t)HD * Dd];      // 2.1 MB

// ---------------------------------------------------------------------------
// Helpers
// ---------------------------------------------------------------------------
__device__ __forceinline__ float lrelu(float x) {
    return x > 0.0f ? x : SLOPE * x;
}

__device__ __forceinline__ uint32_t smem_u32(const void* p) {
    return (uint32_t)__cvta_generic_to_shared(p);
}

__device__ __forceinline__ void ldsm_x4(uint32_t* r, uint32_t addr) {
    asm volatile("ldmatrix.sync.aligned.m8n8.x4.shared.b16 {%0,%1,%2,%3}, [%4];"
                 : "=r"(r[0]), "=r"(r[1]), "=r"(r[2]), "=r"(r[3]) : "r"(addr));
}
__device__ __forceinline__ void ldsm_x4t(uint32_t* r, uint32_t addr) {
    asm volatile("ldmatrix.sync.aligned.m8n8.x4.trans.shared.b16 {%0,%1,%2,%3}, [%4];"
                 : "=r"(r[0]), "=r"(r[1]), "=r"(r[2]), "=r"(r[3]) : "r"(addr));
}
__device__ __forceinline__ void mma16816(float* c, const uint32_t* a, const uint32_t* b) {
    asm volatile("mma.sync.aligned.m16n8k16.row.col.f32.f16.f16.f32 "
                 "{%0,%1,%2,%3}, {%4,%5,%6,%7}, {%8,%9}, {%0,%1,%2,%3};"
                 : "+f"(c[0]), "+f"(c[1]), "+f"(c[2]), "+f"(c[3])
                 : "r"(a[0]), "r"(a[1]), "r"(a[2]), "r"(a[3]),
                   "r"(b[0]), "r"(b[1]));
}

__device__ __forceinline__ void cp_async16(uint32_t saddr, const void* gptr) {
    asm volatile("cp.async.cg.shared.global [%0], [%1], 16;"
                 :: "r"(saddr), "l"(gptr) : "memory");
}
#define CP_COMMIT() asm volatile("cp.async.commit_group;" ::: "memory")
#define CP_WAIT0()  asm volatile("cp.async.wait_group 0;" ::: "memory")
#define CP_WAIT1()  asm volatile("cp.async.wait_group 1;" ::: "memory")

// 8 halves (uint4) -> 8 floats
__device__ __forceinline__ void h8_to_f(uint4 v, float* f) {
    float2 t;
    t = __half22float2(*(const __half2*)&v.x); f[0] = t.x; f[1] = t.y;
    t = __half22float2(*(const __half2*)&v.y); f[2] = t.x; f[3] = t.y;
    t = __half22float2(*(const __half2*)&v.z); f[4] = t.x; f[5] = t.y;
    t = __half22float2(*(const __half2*)&v.w); f[6] = t.x; f[7] = t.y;
}
// 8 floats -> 8 halves (uint4)
__device__ __forceinline__ uint4 f_to_h8(const float* f) {
    uint4 v; __half2 h;
    h = __floats2half2_rn(f[0], f[1]); v.x = *(uint32_t*)&h;
    h = __floats2half2_rn(f[2], f[3]); v.y = *(uint32_t*)&h;
    h = __floats2half2_rn(f[4], f[5]); v.z = *(uint32_t*)&h;
    h = __floats2half2_rn(f[6], f[7]); v.w = *(uint32_t*)&h;
    return v;
}

// ---------------------------------------------------------------------------
// Small setup kernels
// ---------------------------------------------------------------------------
__global__ void k_zero() {
    int idx = blockIdx.x * blockDim.x + threadIdx.x;
    if (idx < Nn) { g_deg[idx] = 0; g_cursor[idx] = 0; }
}

__global__ void k_seed(const float* __restrict__ b_fc) {
    int j = threadIdx.x;
    if (j < Dd) g_effbias[j] = b_fc[j];
}

__global__ void k_catbias(const float* __restrict__ b_src,
                          const float* __restrict__ b_dst) {
    int j = blockIdx.x * blockDim.x + threadIdx.x;
    if (j < HD)           g_biascat[j] = b_src[j];
    else if (j < 2 * HD)  g_biascat[j] = b_dst[j - HD];
}

// ---------------------------------------------------------------------------
// Effective fc bias partials: eff[j] += sum_{k in chunk} gat_bias[k]*W_fc[k,j]
// ---------------------------------------------------------------------------
__global__ __launch_bounds__(512)
void k_fcbias(const float* __restrict__ gat_bias,
              const float* __restrict__ W_fc) {
    int j = threadIdx.x;
    int k0 = blockIdx.x * (HD / 16);
    float acc = 0.f;
    #pragma unroll 8
    for (int k = k0; k < k0 + HD / 16; ++k)
        acc = fmaf(gat_bias[k], W_fc[(size_t)k * Dd + j], acc);
    atomicAdd(&g_effbias[j], acc);
}

// ---------------------------------------------------------------------------
// CSR build over dst
// ---------------------------------------------------------------------------
__global__ void k_hist(const int* __restrict__ dst) {
    int e = blockIdx.x * blockDim.x + threadIdx.x;
    if (e < Ee) atomicAdd(&g_deg[dst[e]], 1);
}

__global__ __launch_bounds__(512)
void k_scan() {
    __shared__ int s[512];
    const int t = threadIdx.x;
    const int CH = (Nn + 511) / 512;
    const int base = t * CH;
    int sum = 0;
    for (int i = 0; i < CH; ++i)
        if (base + i < Nn) sum += g_deg[base + i];
    s[t] = sum;
    __syncthreads();
    for (int off = 1; off < 512; off <<= 1) {
        int v = (t >= off) ? s[t - off] : 0;
        __syncthreads();
        s[t] += v;
        __syncthreads();
    }
    int run = s[t] - sum;
    for (int i = 0; i < CH; ++i) {
        if (base + i < Nn) {
            g_rowptr[base + i] = run;
            run += g_deg[base + i];
        }
    }
}

__global__ void k_scatter(const int* __restrict__ dst) {
    int e = blockIdx.x * blockDim.x + threadIdx.x;
    if (e >= Ee) return;
    int t = dst[e];
    int pos = g_rowptr[t] + atomicAdd(&g_cursor[t], 1);
    g_eidx[pos] = e;
}

// ---------------------------------------------------------------------------
// fp32 -> fp16 casts
// ---------------------------------------------------------------------------
__global__ void k_cvt(const float* __restrict__ X, __half* __restrict__ Y,
                      size_t total4) {
    size_t idx = (size_t)blockIdx.x * blockDim.x + threadIdx.x;
    if (idx >= total4) return;
    float4 x = *(const float4*)(X + idx * 4);
    __half2 p0 = __floats2half2_rn(x.x, x.y);
    __half2 p1 = __floats2half2_rn(x.z, x.w);
    uint2 v; v.x = *(uint32_t*)&p0; v.y = *(uint32_t*)&p1;
    *(uint2*)(Y + idx * 4) = v;
}

// [K,N] fp32 -> [K,Nout] fp16 at column offset (for weight concatenation)
__global__ void k_cvtW(const float* __restrict__ X, __half* __restrict__ Y,
                       int K, int N, int Nout, int colOff) {
    size_t idx = (size_t)blockIdx.x * blockDim.x + threadIdx.x;
    size_t tot = (size_t)K * (N / 4);
    if (idx >= tot) return;
    int k  = (int)(idx / (N / 4));
    int nq = (int)(idx % (N / 4)) * 4;
    float4 x = *(const float4*)(X + (size_t)k * N + nq);
    __half2 p0 = __floats2half2_rn(x.x, x.y);
    __half2 p1 = __floats2half2_rn(x.z, x.w);
    uint2 v; v.x = *(uint32_t*)&p0; v.y = *(uint32_t*)&p1;
    *(uint2*)(Y + (size_t)k * Nout + colOff + nq) = v;
}

// ---------------------------------------------------------------------------
// fp16 tensor-core GEMM: C[M,N] = A[M,K]f16 @ B[K,N]f16 + bias(fp32),
// optional LeakyReLU; output fp16 (HALF_OUT) or fp32.
// 128x128 block tile, BK=32, 8 warps (4x2), warp 32x64,
// 3-stage cp.async pipeline (wait_group 1), dynamic smem, 2 CTAs/SM.
// ---------------------------------------------------------------------------
#define BM 128
#define BN 128
#define BK 32
#define ASTR (BK + 8)
#define BSTR (BN + 8)
#define A_EL (BM * ASTR)
#define B_EL (BK * BSTR)
#define STAGES 3
#define GEMM_SMEM (STAGES * (A_EL + B_EL) * 2)   // 56832 bytes

template<bool HALF_OUT>
__global__ __launch_bounds__(256, 2)
void gemm_f16(const __half* __restrict__ A,
              const __half* __restrict__ B,
              const float* __restrict__ bias, void* __restrict__ Cv,
              int M, int N, int K, int do_lrelu) {
    extern __shared__ __half smh[];
    __half* smA = smh;                     // STAGES * A_EL
    __half* smB = smh + STAGES * A_EL;     // STAGES * B_EL

    const int tid  = threadIdx.x;
    const int lane = tid & 31;
    const int warp = tid >> 5;
    const int mw = (warp & 3) * 32;
    const int nw = (warp >> 2) * 64;

    const int rowBase = blockIdx.y * BM;
    const int colBase = blockIdx.x * BN;

    const int aRow = tid >> 2;            // 0..63 (+64)
    const int aCol = (tid & 3) * 8;
    const int bRow = tid >> 4;            // 0..15 (+16)
    const int bCol = (tid & 15) * 8;

    float acc[2][8][4];
    #pragma unroll
    for (int i = 0; i < 2; ++i)
        #pragma unroll
        for (int j = 0; j < 8; ++j)
            #pragma unroll
            for (int q = 0; q < 4; ++q) acc[i][j][q] = 0.f;

    const int ldRow = lane & 15;
    const int ldOff = (lane >> 4) * 8;

    int aR0 = rowBase + aRow;       if (aR0 > M - 1) aR0 = M - 1;
    int aR1 = rowBase + aRow + 64;  if (aR1 > M - 1) aR1 = M - 1;

    const int nT = K / BK;

    // tile loader: global k0 -> stage buffer
    #define LOAD_TILE(st, k0)                                                           \
        do {                                                                            \
            cp_async16(smem_u32(&smA[(st) * A_EL + aRow * ASTR + aCol]),                \
                       A + (size_t)aR0 * K + (k0) + aCol);                              \
            cp_async16(smem_u32(&smA[(st) * A_EL + (aRow + 64) * ASTR + aCol]),         \
                       A + (size_t)aR1 * K + (k0) + aCol);                              \
            cp_async16(smem_u32(&smB[(st) * B_EL + bRow * BSTR + bCol]),                \
                       B + (size_t)((k0) + bRow) * N + colBase + bCol);                 \
            cp_async16(smem_u32(&smB[(st) * B_EL + (bRow + 16) * BSTR + bCol]),         \
                       B + (size_t)((k0) + bRow + 16) * N + colBase + bCol);            \
            CP_COMMIT();                                                                \
        } while (0)

    // prologue: stage tiles 0 and 1
    LOAD_TILE(0, 0);
    if (nT > 1) LOAD_TILE(1, BK);

    for (int t = 0; t < nT; ++t) {
        // wait for tile t (allow the next tile's load to stay in flight)
        if (t < nT - 1) { CP_WAIT1(); } else { CP_WAIT0(); }
        __syncthreads();   // all threads done computing t-1; tile t visible

        // issue load for tile t+2 into buffer (t+2)%3 (read last at iter t-1)
        if (t + 2 < nT) LOAD_TILE((t + 2) % STAGES, (t + 2) * BK);

        const int cb = t % STAGES;
        #pragma unroll
        for (int ks = 0; ks < 2; ++ks) {
            uint32_t af[2][4];
            #pragma unroll
            for (int mt = 0; mt < 2; ++mt) {
                uint32_t addr = smem_u32(&smA[cb * A_EL + (mw + mt * 16 + ldRow) * ASTR
                                              + ks * 16 + ldOff]);
                ldsm_x4(af[mt], addr);
            }
            uint32_t bfr[8][2];
            #pragma unroll
            for (int np = 0; np < 4; ++np) {
                uint32_t addr = smem_u32(&smB[cb * B_EL + (ks * 16 + ldRow) * BSTR
                                              + nw + np * 16 + ldOff]);
                uint32_t r[4];
                ldsm_x4t(r, addr);
                bfr[np * 2][0] = r[0]; bfr[np * 2][1] = r[1];
                bfr[np * 2 + 1][0] = r[2]; bfr[np * 2 + 1][1] = r[3];
            }
            #pragma unroll
            for (int mt = 0; mt < 2; ++mt)
                #pragma unroll
                for (int nt = 0; nt < 8; ++nt)
                    mma16816(acc[mt][nt], af[mt], bfr[nt]);
        }
    }
    #undef LOAD_TILE

    // ---- epilogue ----
    const int g = lane >> 2;
    const int tq = lane & 3;
    #pragma unroll
    for (int mt = 0; mt < 2; ++mt) {
        #pragma unroll
        for (int nt = 0; nt < 8; ++nt) {
            int col = colBase + nw + nt * 8 + tq * 2;
            float bx = bias[col], by = bias[col + 1];
            #pragma unroll
            for (int hrow = 0; hrow < 2; ++hrow) {
                int row = rowBase + mw + mt * 16 + g + hrow * 8;
                if (row >= M) continue;
                float vx = acc[mt][nt][hrow * 2 + 0] + bx;
                float vy = acc[mt][nt][hrow * 2 + 1] + by;
                if (do_lrelu) { vx = lrelu(vx); vy = lrelu(vy); }
                if (HALF_OUT) {
                    __half2 h = __floats2half2_rn(vx, vy);
                    *(uint32_t*)((__half*)Cv + (size_t)row * N + col) = *(uint32_t*)&h;
                } else {
                    float2 v; v.x = vx; v.y = vy;
                    *(float2*)((float*)Cv + (size_t)row * N + col) = v;
                }
            }
        }
    }
}

// ---------------------------------------------------------------------------
// Fused per-node GAT over fp16 features (row = [fs | fd], stride FW).
// One warp per (node, head). Lanes stage up to 32 edge srcs cooperatively;
// inner loop is software-pipelined: edge i+1's two 16B gathers are issued
// before edge i's math (2x gather MLP).
// ---------------------------------------------------------------------------
__global__ __launch_bounds__(256)
void k_node(const int* __restrict__ src, const float* __restrict__ attn) {
    int gw = blockIdx.x * 8 + (threadIdx.x >> 5);
    if (gw >= Nn * Hh) return;
    const int lane = threadIdx.x & 31;
    const int n = gw >> 2;
    const int h = gw & 3;

    const int start = g_rowptr[n];
    const int d     = g_deg[n];

    const uint4* fd8 = (const uint4*)(g_feat + (size_t)n * FW + HD + h * Dd);
    const float4* at4 = (const float4*)(attn + h * Dd);

    float fdr[16], atr[16];
    #pragma unroll
    for (int q = 0; q < 2; ++q) {
        h8_to_f(fd8[q * 32 + lane], &fdr[q * 8]);
        float4 a0 = at4[(q * 32 + lane) * 2];
        float4 a1 = at4[(q * 32 + lane) * 2 + 1];
        atr[q * 8 + 0] = a0.x; atr[q * 8 + 1] = a0.y;
        atr[q * 8 + 2] = a0.z; atr[q * 8 + 3] = a0.w;
        atr[q * 8 + 4] = a1.x; atr[q * 8 + 5] = a1.y;
        atr[q * 8 + 6] = a1.z; atr[q * 8 + 7] = a1.w;
    }

    float acc[16];
    #pragma unroll
    for (int i = 0; i < 16; ++i) acc[i] = 0.f;
    float denom = 0.f;

    const size_t sliceOff = (size_t)h * (Dd / 8);
    for (int base = 0; base < d; base += 32) {
        int cnt = d - base; if (cnt > 32) cnt = 32;
        int sv = 0;
        if (lane < cnt) sv = src[g_eidx[start + base + lane]];

        // prefetch edge 0 of this block
        int s0 = __shfl_sync(0xffffffffu, sv, 0);
        const uint4* fr = (const uint4*)(g_feat + (size_t)s0 * FW) + sliceOff;
        uint4 v0 = fr[lane];
        uint4 v1 = fr[32 + lane];

        for (int i = 0; i < cnt; ++i) {
            uint4 c0 = v0, c1 = v1;
            if (i + 1 < cnt) {      // issue next edge's gathers before math
                int sn = __shfl_sync(0xffffffffu, sv, i + 1);
                const uint4* fn = (const uint4*)(g_feat + (size_t)sn * FW) + sliceOff;
                v0 = fn[lane];
                v1 = fn[32 + lane];
            }
            float af[16];
            h8_to_f(c0, &af[0]);
            h8_to_f(c1, &af[8]);
            float p = 0.f;
            #pragma unroll
            for (int j = 0; j < 16; ++j)
                p = fmaf(lrelu(af[j] + fdr[j]), atr[j], p);
            #pragma unroll
            for (int o = 16; o; o >>= 1)
                p += __shfl_xor_sync(0xffffffffu, p, o);
            float w = expf(p);
            denom += w;
            #pragma unroll
            for (int j = 0; j < 16; ++j)
                acc[j] = fmaf(w, af[j], acc[j]);
        }
    }

    float inv = (d > 0) ? 1.f / denom : 0.f;
    #pragma unroll
    for (int j = 0; j < 16; ++j) acc[j] *= inv;

    uint4* rp = (uint4*)(g_rp + (size_t)n * HD + h * Dd);
    rp[lane]      = f_to_h8(&acc[0]);
    rp[32 + lane] = f_to_h8(&acc[8]);
}

// ---------------------------------------------------------------------------
// Persistent stream/event handles (created once, never destroyed; nothing
// is created during graph capture so memory checkpoints stay at baseline).
// ---------------------------------------------------------------------------
struct SideStreams {
    cudaStream_t s1, s2;
    cudaEvent_t  evF, ev1, ev2;
    SideStreams() {
        cudaStreamCreateWithFlags(&s1, cudaStreamNonBlocking);
        cudaStreamCreateWithFlags(&s2, cudaStreamNonBlocking);
        cudaEventCreateWithFlags(&evF, cudaEventDisableTiming);
        cudaEventCreateWithFlags(&ev1, cudaEventDisableTiming);
        cudaEventCreateWithFlags(&ev2, cudaEventDisableTiming);
        cudaFuncSetAttribute(gemm_f16<true>,
            cudaFuncAttributeMaxDynamicSharedMemorySize, GEMM_SMEM);
        cudaFuncSetAttribute(gemm_f16<false>,
            cudaFuncAttributeMaxDynamicSharedMemorySize, GEMM_SMEM);
    }
};

// ---------------------------------------------------------------------------
// Launch: three-way stream fork (main: GEMM chain; s1: CSR; s2: bias/W_fc),
// joined before k_node / fc GEMM. Captured into the graph via events.
// ---------------------------------------------------------------------------
extern "C" void kernel_launch(void* const* d_in, const int* in_sizes, int n_in,
                              void* d_out, int out_size) {
    const float* z        = (const float*)d_in[0];
    const int*   src      = (const int*)  d_in[1];
    const int*   dst      = (const int*)  d_in[2];
    const float* W_src    = (const float*)d_in[3];
    const float* b_src    = (const float*)d_in[4];
    const float* W_dst    = (const float*)d_in[5];
    const float* b_dst    = (const float*)d_in[6];
    const float* attn     = (const float*)d_in[7];
    const float* gat_bias = (const float*)d_in[8];
    const float* W_fc     = (const float*)d_in[9];
    const float* b_fc     = (const float*)d_in[10];
    float* out = (float*)d_out;

    void* p;
    cudaGetSymbolAddress(&p, g_feat);    __half* feat = (__half*)p;
    cudaGetSymbolAddress(&p, g_rp);      __half* rp   = (__half*)p;
    cudaGetSymbolAddress(&p, g_effbias); float* eb    = (float*)p;
    cudaGetSymbolAddress(&p, g_biascat); float* bc    = (float*)p;
    cudaGetSymbolAddress(&p, g_zp);      __half* zp   = (__half*)p;
    cudaGetSymbolAddress(&p, g_w);       __half* w    = (__half*)p;
    cudaGetSymbolAddress(&p, g_wfp);     __half* wfp  = (__half*)p;

    static SideStreams ss;   // created on first (correctness) call only

    // fork
    cudaEventRecord(ss.evF, 0);
    cudaStreamWaitEvent(ss.s1, ss.evF, 0);
    cudaStreamWaitEvent(ss.s2, ss.evF, 0);

    // ---- s1: CSR build over dst ----
    k_zero<<<(Nn + 511) / 512, 512, 0, ss.s1>>>();
    k_hist<<<(Ee + 255) / 256, 256, 0, ss.s1>>>(dst);
    k_scan<<<1, 512, 0, ss.s1>>>();
    k_scatter<<<(Ee + 255) / 256, 256, 0, ss.s1>>>(dst);
    cudaEventRecord(ss.ev1, ss.s1);

    // ---- s2: fc bias fold + W_fc cast ----
    k_seed<<<1, 512, 0, ss.s2>>>(b_fc);
    k_fcbias<<<16, 512, 0, ss.s2>>>(gat_bias, W_fc);
    k_cvt<<<((size_t)HD * Dd / 4 + 255) / 256, 256, 0, ss.s2>>>(
        W_fc, wfp, (size_t)HD * Dd / 4);
    cudaEventRecord(ss.ev2, ss.s2);

    // ---- main: casts + fused feature GEMM ----
    k_cvt<<<((size_t)Nn * INDIM / 4 + 255) / 256, 256>>>(z, zp, (size_t)Nn * INDIM / 4);
    k_cvtW<<<((size_t)INDIM * HD / 4 + 255) / 256, 256>>>(W_src, w, INDIM, HD, FW, 0);
    k_cvtW<<<((size_t)INDIM * HD / 4 + 255) / 256, 256>>>(W_dst, w, INDIM, HD, FW, HD);
    k_catbias<<<(FW + 255) / 256, 256>>>(b_src, b_dst);

    // [N,256]f16 @ [256,4096]f16 + biascat -> g_feat fp16 ([fs | fd] rows)
    dim3 g1(FW / BN, (Nn + BM - 1) / BM);
    gemm_f16<true><<<g1, 256, GEMM_SMEM>>>(zp, w, bc, feat, Nn, FW, INDIM, 0);

    // join CSR, then fused per-node attention -> fp16 rp
    cudaStreamWaitEvent(0, ss.ev1, 0);
    k_node<<<(Nn * Hh + 7) / 8, 256>>>(src, attn);

    // join bias path, then fc GEMM + effbias + LeakyReLU -> fp32 out
    cudaStreamWaitEvent(0, ss.ev2, 0);
    dim3 g2(Dd / BN, (Nn + BM - 1) / BM);
    gemm_f16<false><<<g2, 256, GEMM_SMEM>>>(rp, wfp, eb, out, Nn, Dd, HD, 1);
}

// round 17
// speedup vs baseline: 1.0170x; 1.0170x over previous
#include <cuda_runtime.h>
#include <cuda_fp16.h>
#include <math_constants.h>
#include <cstdint>

// Problem constants (fixed by the dataset)
#define Nn   20000
#define Ee   100000
#define INDIM 256
#define Dd   512
#define Hh   4
#define HD   2048        // Hh * Dd
#define FW   (2 * HD)    // fused feature row: [fs | fd]
#define SLOPE 0.2f

// ---------------------------------------------------------------------------
// Scratch (device globals: allocation-free per harness rules)
// ---------------------------------------------------------------------------
__device__ __half g_feat[(size_t)Nn * FW];     // 164 MB: row = [fs(2048) | fd(2048)]
__device__ __half g_rp  [(size_t)Nn * HD];     // 82 MB (aggregated feats)
__device__ float  g_effbias[Dd];
__device__ float  g_biascat[FW];               // [b_src | b_dst]

// CSR over dst (g_esrc holds the SRC NODE ID per sorted edge, not the edge id)
__device__ int g_deg[Nn];
__device__ int g_rowptr[Nn];
__device__ int g_cursor[Nn];
__device__ int g_esrc[Ee];

// fp16 casts
__device__ __half g_zp[(size_t)Nn * INDIM];    // 10.2 MB
__device__ __half g_w [(size_t)INDIM * FW];    // 2.1 MB: [W_src | W_dst] cols
__device__ __half g_wfp[(size_t)HD * Dd];      // 2.1 MB

// ---------------------------------------------------------------------------
// Helpers
// ---------------------------------------------------------------------------
__device__ __forceinline__ float lrelu(float x) {
    return x > 0.0f ? x : SLOPE * x;
}

__device__ __forceinline__ uint32_t smem_u32(const void* p) {
    return (uint32_t)__cvta_generic_to_shared(p);
}

__device__ __forceinline__ void ldsm_x4(uint32_t* r, uint32_t addr) {
    asm volatile("ldmatrix.sync.aligned.m8n8.x4.shared.b16 {%0,%1,%2,%3}, [%4];"
                 : "=r"(r[0]), "=r"(r[1]), "=r"(r[2]), "=r"(r[3]) : "r"(addr));
}
__device__ __forceinline__ void ldsm_x4t(uint32_t* r, uint32_t addr) {
    asm volatile("ldmatrix.sync.aligned.m8n8.x4.trans.shared.b16 {%0,%1,%2,%3}, [%4];"
                 : "=r"(r[0]), "=r"(r[1]), "=r"(r[2]), "=r"(r[3]) : "r"(addr));
}
__device__ __forceinline__ void mma16816(float* c, const uint32_t* a, const uint32_t* b) {
    asm volatile("mma.sync.aligned.m16n8k16.row.col.f32.f16.f16.f32 "
                 "{%0,%1,%2,%3}, {%4,%5,%6,%7}, {%8,%9}, {%0,%1,%2,%3};"
                 : "+f"(c[0]), "+f"(c[1]), "+f"(c[2]), "+f"(c[3])
                 : "r"(a[0]), "r"(a[1]), "r"(a[2]), "r"(a[3]),
                   "r"(b[0]), "r"(b[1]));
}

__device__ __forceinline__ void cp_async16(uint32_t saddr, const void* gptr) {
    asm volatile("cp.async.cg.shared.global [%0], [%1], 16;"
                 :: "r"(saddr), "l"(gptr) : "memory");
}
#define CP_COMMIT() asm volatile("cp.async.commit_group;" ::: "memory")
#define CP_WAIT0()  asm volatile("cp.async.wait_group 0;" ::: "memory")

// 8 halves (uint4) -> 8 floats
__device__ __forceinline__ void h8_to_f(uint4 v, float* f) {
    float2 t;
    t = __half22float2(*(const __half2*)&v.x); f[0] = t.x; f[1] = t.y;
    t = __half22float2(*(const __half2*)&v.y); f[2] = t.x; f[3] = t.y;
    t = __half22float2(*(const __half2*)&v.z); f[4] = t.x; f[5] = t.y;
    t = __half22float2(*(const __half2*)&v.w); f[6] = t.x; f[7] = t.y;
}
// 8 floats -> 8 halves (uint4)
__device__ __forceinline__ uint4 f_to_h8(const float* f) {
    uint4 v; __half2 h;
    h = __floats2half2_rn(f[0], f[1]); v.x = *(uint32_t*)&h;
    h = __floats2half2_rn(f[2], f[3]); v.y = *(uint32_t*)&h;
    h = __floats2half2_rn(f[4], f[5]); v.z = *(uint32_t*)&h;
    h = __floats2half2_rn(f[6], f[7]); v.w = *(uint32_t*)&h;
    return v;
}

// ---------------------------------------------------------------------------
// Small setup kernels
// ---------------------------------------------------------------------------
__global__ void k_zero() {
    int idx = blockIdx.x * blockDim.x + threadIdx.x;
    if (idx < Nn) { g_deg[idx] = 0; g_cursor[idx] = 0; }
}

__global__ void k_seed(const float* __restrict__ b_fc) {
    int j = threadIdx.x;
    if (j < Dd) g_effbias[j] = b_fc[j];
}

__global__ void k_catbias(const float* __restrict__ b_src,
                          const float* __restrict__ b_dst) {
    int j = blockIdx.x * blockDim.x + threadIdx.x;
    if (j < HD)           g_biascat[j] = b_src[j];
    else if (j < 2 * HD)  g_biascat[j] = b_dst[j - HD];
}

// ---------------------------------------------------------------------------
// Effective fc bias partials: eff[j] += sum_{k in chunk} gat_bias[k]*W_fc[k,j]
// ---------------------------------------------------------------------------
__global__ __launch_bounds__(512)
void k_fcbias(const float* __restrict__ gat_bias,
              const float* __restrict__ W_fc) {
    int j = threadIdx.x;
    int k0 = blockIdx.x * (HD / 16);
    float acc = 0.f;
    #pragma unroll 8
    for (int k = k0; k < k0 + HD / 16; ++k)
        acc = fmaf(gat_bias[k], W_fc[(size_t)k * Dd + j], acc);
    atomicAdd(&g_effbias[j], acc);
}

// ---------------------------------------------------------------------------
// CSR build over dst
// ---------------------------------------------------------------------------
__global__ void k_hist(const int* __restrict__ dst) {
    int e = blockIdx.x * blockDim.x + threadIdx.x;
    if (e < Ee) atomicAdd(&g_deg[dst[e]], 1);
}

__global__ __launch_bounds__(512)
void k_scan() {
    __shared__ int s[512];
    const int t = threadIdx.x;
    const int CH = (Nn + 511) / 512;
    const int base = t * CH;
    int sum = 0;
    for (int i = 0; i < CH; ++i)
        if (base + i < Nn) sum += g_deg[base + i];
    s[t] = sum;
    __syncthreads();
    for (int off = 1; off < 512; off <<= 1) {
        int v = (t >= off) ? s[t - off] : 0;
        __syncthreads();
        s[t] += v;
        __syncthreads();
    }
    int run = s[t] - sum;
    for (int i = 0; i < CH; ++i) {
        if (base + i < Nn) {
            g_rowptr[base + i] = run;
            run += g_deg[base + i];
        }
    }
}

// store the SRC NODE ID directly (saves an indirection in k_node)
__global__ void k_scatter(const int* __restrict__ dst,
                          const int* __restrict__ src) {
    int e = blockIdx.x * blockDim.x + threadIdx.x;
    if (e >= Ee) return;
    int t = dst[e];
    int pos = g_rowptr[t] + atomicAdd(&g_cursor[t], 1);
    g_esrc[pos] = src[e];
}

// ---------------------------------------------------------------------------
// fp32 -> fp16 casts
// ---------------------------------------------------------------------------
__global__ void k_cvt(const float* __restrict__ X, __half* __restrict__ Y,
                      size_t total4) {
    size_t idx = (size_t)blockIdx.x * blockDim.x + threadIdx.x;
    if (idx >= total4) return;
    float4 x = *(const float4*)(X + idx * 4);
    __half2 p0 = __floats2half2_rn(x.x, x.y);
    __half2 p1 = __floats2half2_rn(x.z, x.w);
    uint2 v; v.x = *(uint32_t*)&p0; v.y = *(uint32_t*)&p1;
    *(uint2*)(Y + idx * 4) = v;
}

// [K,N] fp32 -> [K,Nout] fp16 at column offset (for weight concatenation)
__global__ void k_cvtW(const float* __restrict__ X, __half* __restrict__ Y,
                       int K, int N, int Nout, int colOff) {
    size_t idx = (size_t)blockIdx.x * blockDim.x + threadIdx.x;
    size_t tot = (size_t)K * (N / 4);
    if (idx >= tot) return;
    int k  = (int)(idx / (N / 4));
    int nq = (int)(idx % (N / 4)) * 4;
    float4 x = *(const float4*)(X + (size_t)k * N + nq);
    __half2 p0 = __floats2half2_rn(x.x, x.y);
    __half2 p1 = __floats2half2_rn(x.z, x.w);
    uint2 v; v.x = *(uint32_t*)&p0; v.y = *(uint32_t*)&p1;
    *(uint2*)(Y + (size_t)k * Nout + colOff + nq) = v;
}

// ---------------------------------------------------------------------------
// fp16 tensor-core GEMM: C[M,N] = A[M,K]f16 @ B[K,N]f16 + bias(fp32),
// optional LeakyReLU; output fp16 (HALF_OUT) or fp32.
// 128x128 block tile, BK=32, 8 warps (4x2), warp 32x64,
// cp.async double-buffered smem staging, fp32 accumulate, 2 CTAs/SM.
// (R14-proven configuration, unchanged.)
// ---------------------------------------------------------------------------
#define BM 128
#define BN 128
#define BK 32
#define ASTR (BK + 8)
#define BSTR (BN + 8)

template<bool HALF_OUT>
__global__ __launch_bounds__(256, 2)
void gemm_f16(const __half* __restrict__ A,
              const __half* __restrict__ B,
              const float* __restrict__ bias, void* __restrict__ Cv,
              int M, int N, int K, int do_lrelu) {
    __shared__ __half As[2][BM * ASTR];
    __shared__ __half Bs[2][BK * BSTR];

    const int tid  = threadIdx.x;
    const int lane = tid & 31;
    const int warp = tid >> 5;
    const int mw = (warp & 3) * 32;
    const int nw = (warp >> 2) * 64;

    const int rowBase = blockIdx.y * BM;
    const int colBase = blockIdx.x * BN;

    const int aRow = tid >> 2;            // 0..63 (+64)
    const int aCol = (tid & 3) * 8;
    const int bRow = tid >> 4;            // 0..15 (+16)
    const int bCol = (tid & 15) * 8;

    float acc[2][8][4];
    #pragma unroll
    for (int i = 0; i < 2; ++i)
        #pragma unroll
        for (int j = 0; j < 8; ++j)
            #pragma unroll
            for (int q = 0; q < 4; ++q) acc[i][j][q] = 0.f;

    const int ldRow = lane & 15;
    const int ldOff = (lane >> 4) * 8;

    int aR0 = rowBase + aRow;       if (aR0 > M - 1) aR0 = M - 1;
    int aR1 = rowBase + aRow + 64;  if (aR1 > M - 1) aR1 = M - 1;

    // ---- prologue ----
    cp_async16(smem_u32(&As[0][aRow * ASTR + aCol]),        A + (size_t)aR0 * K + aCol);
    cp_async16(smem_u32(&As[0][(aRow + 64) * ASTR + aCol]), A + (size_t)aR1 * K + aCol);
    cp_async16(smem_u32(&Bs[0][bRow * BSTR + bCol]),        B + (size_t)bRow * N + colBase + bCol);
    cp_async16(smem_u32(&Bs[0][(bRow + 16) * BSTR + bCol]), B + (size_t)(bRow + 16) * N + colBase + bCol);
    CP_COMMIT();
    CP_WAIT0();
    __syncthreads();

    const int nT = K / BK;
    int cur = 0;
    for (int t = 0; t < nT; ++t) {
        if (t + 1 < nT) {
            const int nxt = cur ^ 1;
            const int k0 = (t + 1) * BK;
            cp_async16(smem_u32(&As[nxt][aRow * ASTR + aCol]),        A + (size_t)aR0 * K + k0 + aCol);
            cp_async16(smem_u32(&As[nxt][(aRow + 64) * ASTR + aCol]), A + (size_t)aR1 * K + k0 + aCol);
            cp_async16(smem_u32(&Bs[nxt][bRow * BSTR + bCol]),        B + (size_t)(k0 + bRow) * N + colBase + bCol);
            cp_async16(smem_u32(&Bs[nxt][(bRow + 16) * BSTR + bCol]), B + (size_t)(k0 + bRow + 16) * N + colBase + bCol);
            CP_COMMIT();
        }

        #pragma unroll
        for (int ks = 0; ks < 2; ++ks) {
            uint32_t af[2][4];
            #pragma unroll
            for (int mt = 0; mt < 2; ++mt) {
                uint32_t addr = smem_u32(&As[cur][(mw + mt * 16 + ldRow) * ASTR
                                                  + ks * 16 + ldOff]);
                ldsm_x4(af[mt], addr);
            }
            uint32_t bfr[8][2];
            #pragma unroll
            for (int np = 0; np < 4; ++np) {
                uint32_t addr = smem_u32(&Bs[cur][(ks * 16 + ldRow) * BSTR
                                                  + nw + np * 16 + ldOff]);
                uint32_t r[4];
                ldsm_x4t(r, addr);
                bfr[np * 2][0] = r[0]; bfr[np * 2][1] = r[1];
                bfr[np * 2 + 1][0] = r[2]; bfr[np * 2 + 1][1] = r[3];
            }
            #pragma unroll
            for (int mt = 0; mt < 2; ++mt)
                #pragma unroll
                for (int nt = 0; nt < 8; ++nt)
                    mma16816(acc[mt][nt], af[mt], bfr[nt]);
        }

        if (t + 1 < nT) {
            CP_WAIT0();
            __syncthreads();
            cur ^= 1;
        }
    }

    // ---- epilogue ----
    const int g = lane >> 2;
    const int tq = lane & 3;
    #pragma unroll
    for (int mt = 0; mt < 2; ++mt) {
        #pragma unroll
        for (int nt = 0; nt < 8; ++nt) {
            int col = colBase + nw + nt * 8 + tq * 2;
            float bx = bias[col], by = bias[col + 1];
            #pragma unroll
            for (int hrow = 0; hrow < 2; ++hrow) {
                int row = rowBase + mw + mt * 16 + g + hrow * 8;
                if (row >= M) continue;
                float vx = acc[mt][nt][hrow * 2 + 0] + bx;
                float vy = acc[mt][nt][hrow * 2 + 1] + by;
                if (do_lrelu) { vx = lrelu(vx); vy = lrelu(vy); }
                if (HALF_OUT) {
                    __half2 h = __floats2half2_rn(vx, vy);
                    *(uint32_t*)((__half*)Cv + (size_t)row * N + col) = *(uint32_t*)&h;
                } else {
                    float2 v; v.x = vx; v.y = vy;
                    *(float2*)((float*)Cv + (size_t)row * N + col) = v;
                }
            }
        }
    }
}

// ---------------------------------------------------------------------------
// Fused per-node GAT over fp16 features (row = [fs | fd], stride FW).
// One warp per (node, head). Lanes stage up to 32 src ids cooperatively
// (g_esrc already holds src node ids), then single pass:
// w=exp(score), denom += w, acc += w * fs[src].
// ---------------------------------------------------------------------------
__global__ __launch_bounds__(256)
void k_node(const float* __restrict__ attn) {
    int gw = blockIdx.x * 8 + (threadIdx.x >> 5);
    if (gw >= Nn * Hh) return;
    const int lane = threadIdx.x & 31;
    const int n = gw >> 2;
    const int h = gw & 3;

    const int start = g_rowptr[n];
    const int d     = g_deg[n];

    const uint4* fd8 = (const uint4*)(g_feat + (size_t)n * FW + HD + h * Dd);
    const float4* at4 = (const float4*)(attn + h * Dd);

    float fdr[16], atr[16];
    #pragma unroll
    for (int q = 0; q < 2; ++q) {
        h8_to_f(fd8[q * 32 + lane], &fdr[q * 8]);
        float4 a0 = at4[(q * 32 + lane) * 2];
        float4 a1 = at4[(q * 32 + lane) * 2 + 1];
        atr[q * 8 + 0] = a0.x; atr[q * 8 + 1] = a0.y;
        atr[q * 8 + 2] = a0.z; atr[q * 8 + 3] = a0.w;
        atr[q * 8 + 4] = a1.x; atr[q * 8 + 5] = a1.y;
        atr[q * 8 + 6] = a1.z; atr[q * 8 + 7] = a1.w;
    }

    float acc[16];
    #pragma unroll
    for (int i = 0; i < 16; ++i) acc[i] = 0.f;
    float denom = 0.f;

    const size_t sliceOff = (size_t)h * (Dd / 8);
    for (int base = 0; base < d; base += 32) {
        int cnt = d - base; if (cnt > 32) cnt = 32;
        int sv = 0;
        if (lane < cnt) sv = g_esrc[start + base + lane];
        for (int i = 0; i < cnt; ++i) {
            int s = __shfl_sync(0xffffffffu, sv, i);
            const uint4* fr = (const uint4*)(g_feat + (size_t)s * FW) + sliceOff;
            float af[16];
            float p = 0.f;
            #pragma unroll
            for (int q = 0; q < 2; ++q) {
                h8_to_f(fr[q * 32 + lane], &af[q * 8]);
                #pragma unroll
                for (int j = 0; j < 8; ++j)
                    p = fmaf(lrelu(af[q * 8 + j] + fdr[q * 8 + j]), atr[q * 8 + j], p);
            }
            #pragma unroll
            for (int o = 16; o; o >>= 1)
                p += __shfl_xor_sync(0xffffffffu, p, o);
            float w = expf(p);
            denom += w;
            #pragma unroll
            for (int j = 0; j < 16; ++j)
                acc[j] = fmaf(w, af[j], acc[j]);
        }
    }

    float inv = (d > 0) ? 1.f / denom : 0.f;
    #pragma unroll
    for (int j = 0; j < 16; ++j) acc[j] *= inv;

    uint4* rp = (uint4*)(g_rp + (size_t)n * HD + h * Dd);
    rp[lane]      = f_to_h8(&acc[0]);
    rp[32 + lane] = f_to_h8(&acc[8]);
}

// ---------------------------------------------------------------------------
// Persistent stream/event handles — EXACT R14 shape (3 streams, 5 events),
// the configuration proven to pass the teardown memory checks. Created once
// on the first (correctness) call, reused forever.
// ---------------------------------------------------------------------------
struct SideStreams {
    cudaStream_t s1, s2;
    cudaEvent_t  evF, ev1, ev2;
    SideStreams() {
        cudaStreamCreateWithFlags(&s1, cudaStreamNonBlocking);
        cudaStreamCreateWithFlags(&s2, cudaStreamNonBlocking);
        cudaEventCreateWithFlags(&evF, cudaEventDisableTiming);
        cudaEventCreateWithFlags(&ev1, cudaEventDisableTiming);
        cudaEventCreateWithFlags(&ev2, cudaEventDisableTiming);
    }
};

// ---------------------------------------------------------------------------
// Launch: three-way stream fork (main: GEMM chain; s1: CSR; s2: bias/W_fc),
// joined before k_node / fc GEMM. Captured into the graph via events.
// ---------------------------------------------------------------------------
extern "C" void kernel_launch(void* const* d_in, const int* in_sizes, int n_in,
                              void* d_out, int out_size) {
    const float* z        = (const float*)d_in[0];
    const int*   src      = (const int*)  d_in[1];
    const int*   dst      = (const int*)  d_in[2];
    const float* W_src    = (const float*)d_in[3];
    const float* b_src    = (const float*)d_in[4];
    const float* W_dst    = (const float*)d_in[5];
    const float* b_dst    = (const float*)d_in[6];
    const float* attn     = (const float*)d_in[7];
    const float* gat_bias = (const float*)d_in[8];
    const float* W_fc     = (const float*)d_in[9];
    const float* b_fc     = (const float*)d_in[10];
    float* out = (float*)d_out;

    void* p;
    cudaGetSymbolAddress(&p, g_feat);    __half* feat = (__half*)p;
    cudaGetSymbolAddress(&p, g_rp);      __half* rp   = (__half*)p;
    cudaGetSymbolAddress(&p, g_effbias); float* eb    = (float*)p;
    cudaGetSymbolAddress(&p, g_biascat); float* bc    = (float*)p;
    cudaGetSymbolAddress(&p, g_zp);      __half* zp   = (__half*)p;
    cudaGetSymbolAddress(&p, g_w);       __half* w    = (__half*)p;
    cudaGetSymbolAddress(&p, g_wfp);     __half* wfp  = (__half*)p;

    static SideStreams ss;   // created on first (correctness) call only

    // fork
    cudaEventRecord(ss.evF, 0);
    cudaStreamWaitEvent(ss.s1, ss.evF, 0);
    cudaStreamWaitEvent(ss.s2, ss.evF, 0);

    // ---- s1: CSR build over dst ----
    k_zero<<<(Nn + 511) / 512, 512, 0, ss.s1>>>();
    k_hist<<<(Ee + 255) / 256, 256, 0, ss.s1>>>(dst);
    k_scan<<<1, 512, 0, ss.s1>>>();
    k_scatter<<<(Ee + 255) / 256, 256, 0, ss.s1>>>(dst, src);
    cudaEventRecord(ss.ev1, ss.s1);

    // ---- s2: fc bias fold + W_fc cast ----
    k_seed<<<1, 512, 0, ss.s2>>>(b_fc);
    k_fcbias<<<16, 512, 0, ss.s2>>>(gat_bias, W_fc);
    k_cvt<<<((size_t)HD * Dd / 4 + 255) / 256, 256, 0, ss.s2>>>(
        W_fc, wfp, (size_t)HD * Dd / 4);
    cudaEventRecord(ss.ev2, ss.s2);

    // ---- main: casts + fused feature GEMM ----
    k_cvt<<<((size_t)Nn * INDIM / 4 + 255) / 256, 256>>>(z, zp, (size_t)Nn * INDIM / 4);
    k_cvtW<<<((size_t)INDIM * HD / 4 + 255) / 256, 256>>>(W_src, w, INDIM, HD, FW, 0);
    k_cvtW<<<((size_t)INDIM * HD / 4 + 255) / 256, 256>>>(W_dst, w, INDIM, HD, FW, HD);
    k_catbias<<<(FW + 255) / 256, 256>>>(b_src, b_dst);

    // [N,256]f16 @ [256,4096]f16 + biascat -> g_feat fp16 ([fs | fd] rows)
    dim3 g1(FW / BN, (Nn + BM - 1) / BM);
    gemm_f16<true><<<g1, 256>>>(zp, w, bc, feat, Nn, FW, INDIM, 0);

    // join CSR, then fused per-node attention -> fp16 rp
    cudaStreamWaitEvent(0, ss.ev1, 0);
    k_node<<<(Nn * Hh + 7) / 8, 256>>>(attn);

    // join bias path, then fc GEMM + effbias + LeakyReLU -> fp32 out
    cudaStreamWaitEvent(0, ss.ev2, 0);
    dim3 g2(Dd / BN, (Nn + BM - 1) / BM);
    gemm_f16<false><<<g2, 256>>>(rp, wfp, eb, out, Nn, Dd, HD, 1);
}